// round 2
// baseline (speedup 1.0000x reference)
#include <cuda_runtime.h>
#include <cstdint>

// SparseLayer: b=8, n=4096, CHUNK=32 -> c=128 chunks/batch, RANK=2,
// 8 points per gaussian (4 neighbor + 2 global + 2 local), 256 points/chunk.
#define B        8
#define NPOS     4096
#define CHUNK    32
#define NCHUNK   128      // 4096/32
#define PTS      256      // 32*8
#define OUT_DIM  1024
#define IN_DIM   1024
#define EPS      1e-6f

// ---------------------------------------------------------------------------
// Threefry-2x32, 20 rounds — bit-exact replica of jax._src.prng.threefry2x32
// ---------------------------------------------------------------------------
__host__ __device__ __forceinline__ void tf2x32(uint32_t k0, uint32_t k1,
                                                uint32_t c0, uint32_t c1,
                                                uint32_t& o0, uint32_t& o1) {
    uint32_t ks2 = k0 ^ k1 ^ 0x1BD11BDAu;
    uint32_t x0 = c0 + k0, x1 = c1 + k1;
#define TF_ROUND(r) { x0 += x1; x1 = (x1 << (r)) | (x1 >> (32 - (r))); x1 ^= x0; }
    TF_ROUND(13) TF_ROUND(15) TF_ROUND(26) TF_ROUND(6)
    x0 += k1;  x1 += ks2 + 1u;
    TF_ROUND(17) TF_ROUND(29) TF_ROUND(16) TF_ROUND(24)
    x0 += ks2; x1 += k0 + 2u;
    TF_ROUND(13) TF_ROUND(15) TF_ROUND(26) TF_ROUND(6)
    x0 += k0;  x1 += k1 + 3u;
    TF_ROUND(17) TF_ROUND(29) TF_ROUND(16) TF_ROUND(24)
    x0 += k1;  x1 += ks2 + 4u;
    TF_ROUND(13) TF_ROUND(15) TF_ROUND(26) TF_ROUND(6)
    x0 += ks2; x1 += k0 + 5u;
#undef TF_ROUND
    o0 = x0; o1 = x1;
}

// jax_threefry_partitionable=True (modern default) random_bits, 32-bit:
// element e (flat, row-major) -> (b1,b2) = threefry(key, (hi32(e), lo32(e)));
// bits = b1 ^ b2.   Here e < 2^32 so hi = 0.
__device__ __forceinline__ uint32_t rand_bits_part(uint32_t k0, uint32_t k1,
                                                   uint32_t e) {
    uint32_t o0, o1;
    tf2x32(k0, k1, 0u, e, o0, o1);
    return o0 ^ o1;
}

// jax.random.uniform float conversion: bitcast((bits>>9)|0x3f800000) - 1.0
__device__ __forceinline__ float u01(uint32_t bits) {
    return __uint_as_float((bits >> 9) | 0x3F800000u) - 1.0f;
}

// ---------------------------------------------------------------------------
// Kernel 1: y[b][o] = bias[o]
// ---------------------------------------------------------------------------
__global__ void sl_init_kernel(const float* __restrict__ bias,
                               float* __restrict__ y) {
    int i = blockIdx.x * blockDim.x + threadIdx.x;
    if (i < B * OUT_DIM) y[i] = bias[i & (OUT_DIM - 1)];
}

// ---------------------------------------------------------------------------
// Kernel 2: one block per (chunk, batch); 256 threads = 256 points.
// ---------------------------------------------------------------------------
__global__ __launch_bounds__(256) void sl_chunk_kernel(
    const float* __restrict__ x,       // (B, IN_DIM)
    const float* __restrict__ means,   // (B, NPOS, 2)
    const float* __restrict__ sigmas,  // (B, NPOS, 2)
    const float* __restrict__ values,  // (B, NPOS)
    float* __restrict__ y,             // (B, OUT_DIM)
    uint32_t kg0, uint32_t kg1, uint32_t kl0, uint32_t kl1)
{
    __shared__ float sm0[CHUNK], sm1[CHUNK];   // means per gaussian
    __shared__ float sw0[CHUNK], sw1[CHUNK];   // 1/(eps+sigma)
    __shared__ float sval[CHUNK];
    __shared__ int   scode[PTS];
    __shared__ float sprops[PTS][CHUNK + 1];   // pad to 33 -> conflict-free
    __shared__ float spart[8][CHUNK];
    __shared__ float svv[CHUNK];               // values[k]/colsum[k]

    const int tid   = threadIdx.x;             // 0..255
    const int cc    = blockIdx.x;              // 0..127
    const int bb    = blockIdx.y;              // 0..7
    const int k     = tid >> 3;                // gaussian 0..31
    const int which = tid & 7;                 // point kind 0..7

    if (tid < CHUNK) {
        int pos  = bb * NPOS + cc * CHUNK + tid;
        int base = pos * 2;
        sm0[tid]  = means[base];
        sm1[tid]  = means[base + 1];
        sw0[tid]  = 1.0f / (EPS + sigmas[base]);
        sw1[tid]  = 1.0f / (EPS + sigmas[base + 1]);
        sval[tid] = values[pos];
    }
    __syncthreads();

    const float m0 = sm0[k], m1 = sm1[k];
    int o, j;

    if (which < 4) {
        // FLOOR_MASK rows: (T,T),(T,F),(F,T),(F,F); True -> floor
        float f0 = (which < 2)        ? floorf(m0) : ceilf(m0);
        float f1 = ((which & 1) == 0) ? floorf(m1) : ceilf(m1);
        o = (int)f0;
        j = (int)f1;
    } else if (which < 6) {
        // global ints: floor(u*(1-eps) * 1024)
        int g = which - 4;
        uint32_t e = (uint32_t)(bb * 16384 + cc * 128 + k * 4 + g * 2);
        float u0 = u01(rand_bits_part(kg0, kg1, e));
        float u1 = u01(rand_bits_part(kg0, kg1, e + 1));
        o = (int)floorf(__fmul_rn(__fmul_rn(u0, 1.0f - EPS), 1024.0f));
        j = (int)floorf(__fmul_rn(__fmul_rn(u1, 1.0f - EPS), 1024.0f));
    } else {
        // local ints: (u*(1-eps)*16 + lower), truncated
        int l = which - 6;
        uint32_t e = (uint32_t)(bb * 16384 + cc * 128 + k * 4 + l * 2);
        float u0 = u01(rand_bits_part(kl0, kl1, e));
        float u1 = u01(rand_bits_part(kl0, kl1, e + 1));
        float mn0 = rintf(m0), mn1 = rintf(m1);       // jnp.round = half-to-even
        float lo0 = mn0 - 8.0f, lo1 = mn1 - 8.0f;
        if (lo0 < 0.0f) lo0 = 0.0f;
        if (mn0 + 8.0f > 1024.0f) lo0 = 1008.0f;
        if (lo1 < 0.0f) lo1 = 0.0f;
        if (mn1 + 8.0f > 1024.0f) lo1 = 1008.0f;
        float lu0 = __fmul_rn(u0, 1.0f - EPS);
        float lu1 = __fmul_rn(u1, 1.0f - EPS);
        o = (int)__fadd_rn(__fmul_rn(lu0, 16.0f), lo0);
        j = (int)__fadd_rn(__fmul_rn(lu1, 16.0f), lo1);
    }

    const int code = o * IN_DIM + j;
    scode[tid] = code;
    __syncthreads();

    bool dup = false;
    for (int t = 0; t < tid; t++)
        if (scode[t] == code) dup = true;

    // densities row (zeroed if dup, matching reference's pre-sum masking)
    const float po = (float)o, pj = (float)j;
    #pragma unroll 8
    for (int kk = 0; kk < CHUNK; kk++) {
        float d0 = po - sm0[kk];
        float d1 = pj - sm1[kk];
        float s  = d0 * d0 * sw0[kk] + d1 * d1 * sw1[kk];
        sprops[tid][kk] = dup ? 0.0f : expf(-0.5f * s);
    }
    __syncthreads();

    // column sums over 256 points (two-level: 8 groups x 32 rows)
    {
        int col = tid & 31, grp = tid >> 5;
        float s = 0.0f;
        int r0 = grp * 32;
        #pragma unroll 8
        for (int r = 0; r < 32; r++) s += sprops[r0 + r][col];
        spart[grp][col] = s;
    }
    __syncthreads();
    if (tid < CHUNK) {
        float s = 0.0f;
        #pragma unroll
        for (int g = 0; g < 8; g++) s += spart[g][tid];
        svv[tid] = sval[tid] / s;
    }
    __syncthreads();

    if (!dup) {
        float v = 0.0f;
        #pragma unroll 8
        for (int kk = 0; kk < CHUNK; kk++)
            v += sprops[tid][kk] * svv[kk];
        float contrib = v * x[bb * IN_DIM + j];
        atomicAdd(&y[bb * OUT_DIM + o], contrib);
    }
}

// ---------------------------------------------------------------------------
// Launch
// ---------------------------------------------------------------------------
extern "C" void kernel_launch(void* const* d_in, const int* in_sizes, int n_in,
                              void* d_out, int out_size) {
    const float* x      = (const float*)d_in[0];
    const float* means  = (const float*)d_in[1];
    const float* sigmas = (const float*)d_in[2];
    const float* values = (const float*)d_in[3];
    const float* bias   = (const float*)d_in[4];
    float* y = (float*)d_out;

    // key = jax.random.key(42) -> (0, 42)
    // Partitionable (fold-like) split: child key i = threefry(key, (0, i)),
    // taking BOTH output words as the child key.
    uint32_t kg0, kg1, kl0, kl1;
    tf2x32(0u, 42u, 0u, 0u, kg0, kg1);   // kg = split(key)[0]
    tf2x32(0u, 42u, 0u, 1u, kl0, kl1);   // kl = split(key)[1]

    sl_init_kernel<<<(B * OUT_DIM + 255) / 256, 256>>>(bias, y);

    dim3 grid(NCHUNK, B);
    sl_chunk_kernel<<<grid, 256>>>(x, means, sigmas, values, y,
                                   kg0, kg1, kl0, kl1);
}

// round 3
// speedup vs baseline: 1.3057x; 1.3057x over previous
#include <cuda_runtime.h>
#include <cstdint>

#define B        8
#define NPOS     4096
#define CHUNK    32
#define NCHUNK   128
#define PTS      256
#define OUT_DIM  1024
#define IN_DIM   1024
#define EPS      1e-6f
#define ROWP     36      // sprops row stride (floats): 16B-aligned, conflict-free

// ---------------------------------------------------------------------------
// Threefry-2x32, 20 rounds
// ---------------------------------------------------------------------------
__host__ __device__ __forceinline__ void tf2x32(uint32_t k0, uint32_t k1,
                                                uint32_t c0, uint32_t c1,
                                                uint32_t& o0, uint32_t& o1) {
    uint32_t ks2 = k0 ^ k1 ^ 0x1BD11BDAu;
    uint32_t x0 = c0 + k0, x1 = c1 + k1;
#define TF_ROUND(r) { x0 += x1; x1 = (x1 << (r)) | (x1 >> (32 - (r))); x1 ^= x0; }
    TF_ROUND(13) TF_ROUND(15) TF_ROUND(26) TF_ROUND(6)
    x0 += k1;  x1 += ks2 + 1u;
    TF_ROUND(17) TF_ROUND(29) TF_ROUND(16) TF_ROUND(24)
    x0 += ks2; x1 += k0 + 2u;
    TF_ROUND(13) TF_ROUND(15) TF_ROUND(26) TF_ROUND(6)
    x0 += k0;  x1 += k1 + 3u;
    TF_ROUND(17) TF_ROUND(29) TF_ROUND(16) TF_ROUND(24)
    x0 += k1;  x1 += ks2 + 4u;
    TF_ROUND(13) TF_ROUND(15) TF_ROUND(26) TF_ROUND(6)
    x0 += ks2; x1 += k0 + 5u;
#undef TF_ROUND
    o0 = x0; o1 = x1;
}

// partitionable random_bits (32-bit): bits(e) = x0^x1 of threefry(key,(0,e))
__device__ __forceinline__ uint32_t rand_bits_part(uint32_t k0, uint32_t k1,
                                                   uint32_t e) {
    uint32_t o0, o1;
    tf2x32(k0, k1, 0u, e, o0, o1);
    return o0 ^ o1;
}

__device__ __forceinline__ float u01(uint32_t bits) {
    return __uint_as_float((bits >> 9) | 0x3F800000u) - 1.0f;
}

// ---------------------------------------------------------------------------
__global__ void sl_init_kernel(const float* __restrict__ bias,
                               float* __restrict__ y) {
    int i = blockIdx.x * blockDim.x + threadIdx.x;
    if (i < B * OUT_DIM) y[i] = bias[i & (OUT_DIM - 1)];
}

// ---------------------------------------------------------------------------
// One block per (chunk, batch); 256 threads = 256 candidate points.
// ---------------------------------------------------------------------------
__global__ __launch_bounds__(256) void sl_chunk_kernel(
    const float* __restrict__ x,
    const float* __restrict__ means,
    const float* __restrict__ sigmas,
    const float* __restrict__ values,
    float* __restrict__ y,
    uint32_t kg0, uint32_t kg1, uint32_t kl0, uint32_t kl1)
{
    __shared__ __align__(16) float4 sg[CHUNK];         // (m0, m1, w0, w1), w=1/(eps+sig)
    __shared__ float sval[CHUNK];
    __shared__ __align__(16) int   scode[PTS];
    __shared__ __align__(16) float sprops[PTS][ROWP];
    __shared__ float spart[8][CHUNK];
    __shared__ __align__(16) float svv[CHUNK];

    const int tid   = threadIdx.x;
    const int cc    = blockIdx.x;
    const int bb    = blockIdx.y;
    const int k     = tid >> 3;
    const int which = tid & 7;
    const int lane  = tid & 31;
    const int warp  = tid >> 5;

    if (tid < CHUNK) {
        int pos = bb * NPOS + cc * CHUNK + tid;
        float2 mm = ((const float2*)means)[pos];
        float2 ss = ((const float2*)sigmas)[pos];
        sg[tid] = make_float4(mm.x, mm.y,
                              1.0f / (EPS + ss.x), 1.0f / (EPS + ss.y));
        sval[tid] = values[pos];
    }
    __syncthreads();

    const float4 g = sg[k];
    const float m0 = g.x, m1 = g.y;
    int o, j;

    if (which < 4) {
        // FLOOR_MASK rows: (T,T),(T,F),(F,T),(F,F); True -> floor
        float f0 = (which < 2)        ? floorf(m0) : ceilf(m0);
        float f1 = ((which & 1) == 0) ? floorf(m1) : ceilf(m1);
        o = (int)f0;
        j = (int)f1;
    } else {
        // global (which 4,5) and local (which 6,7) share the same flat element
        // index; only the key differs.
        bool isg = (which < 6);
        uint32_t e  = (uint32_t)(bb * 16384 + cc * 128 + k * 4 + (which & 1) * 2);
        uint32_t key0 = isg ? kg0 : kl0;
        uint32_t key1 = isg ? kg1 : kl1;
        float u0 = u01(rand_bits_part(key0, key1, e));
        float u1 = u01(rand_bits_part(key0, key1, e + 1));
        float lu0 = __fmul_rn(u0, 1.0f - EPS);
        float lu1 = __fmul_rn(u1, 1.0f - EPS);
        if (isg) {
            o = (int)floorf(__fmul_rn(lu0, 1024.0f));
            j = (int)floorf(__fmul_rn(lu1, 1024.0f));
        } else {
            float mn0 = rintf(m0), mn1 = rintf(m1);
            float lo0 = mn0 - 8.0f, lo1 = mn1 - 8.0f;
            if (lo0 < 0.0f) lo0 = 0.0f;
            if (mn0 + 8.0f > 1024.0f) lo0 = 1008.0f;
            if (lo1 < 0.0f) lo1 = 0.0f;
            if (mn1 + 8.0f > 1024.0f) lo1 = 1008.0f;
            o = (int)__fadd_rn(__fmul_rn(lu0, 16.0f), lo0);
            j = (int)__fadd_rn(__fmul_rn(lu1, 16.0f), lo1);
        }
    }

    const int code = o * IN_DIM + j;
    scode[tid] = code;
    __syncthreads();

    // duplicate detection: match_any within own warp + vec4 scan of earlier warps
    unsigned mmask = __match_any_sync(0xffffffffu, code);
    bool dup = (mmask & ((1u << lane) - 1u)) != 0u;
    {
        const int4* sc4 = (const int4*)scode;
        const int n4 = warp * 8;
        for (int t = 0; t < n4; t++) {
            int4 c = sc4[t];
            dup |= (c.x == code) | (c.y == code) | (c.z == code) | (c.w == code);
        }
    }

    // densities row: 4 at a time in registers, STS.128
    const float po = (float)o, pj = (float)j;
    const float zmask = dup ? 0.0f : 1.0f;
    #pragma unroll
    for (int q = 0; q < CHUNK / 4; q++) {
        float pv[4];
        #pragma unroll
        for (int u = 0; u < 4; u++) {
            float4 gk = sg[q * 4 + u];
            float d0 = po - gk.x;
            float d1 = pj - gk.y;
            float s  = fmaf(d0 * d0, gk.z, d1 * d1 * gk.w);
            pv[u] = zmask * expf(-0.5f * s);
        }
        *(float4*)&sprops[tid][q * 4] =
            make_float4(pv[0], pv[1], pv[2], pv[3]);
    }
    __syncthreads();

    // column sums over 256 points (8 groups x 32 rows, then stage 2)
    {
        int col = lane, grp = warp;
        float s = 0.0f;
        int r0 = grp * 32;
        #pragma unroll 8
        for (int r = 0; r < 32; r++) s += sprops[r0 + r][col];
        spart[grp][col] = s;
    }
    __syncthreads();
    if (tid < CHUNK) {
        float s = 0.0f;
        #pragma unroll
        for (int gI = 0; gI < 8; gI++) s += spart[gI][tid];
        svv[tid] = sval[tid] / s;
    }
    __syncthreads();

    if (!dup) {
        const float4* row = (const float4*)&sprops[tid][0];
        const float4* vv4 = (const float4*)svv;
        float v = 0.0f;
        #pragma unroll
        for (int q = 0; q < CHUNK / 4; q++) {
            float4 p = row[q];
            float4 w = vv4[q];
            v = fmaf(p.x, w.x, v);
            v = fmaf(p.y, w.y, v);
            v = fmaf(p.z, w.z, v);
            v = fmaf(p.w, w.w, v);
        }
        float contrib = v * x[bb * IN_DIM + j];
        atomicAdd(&y[bb * OUT_DIM + o], contrib);
    }
}

// ---------------------------------------------------------------------------
extern "C" void kernel_launch(void* const* d_in, const int* in_sizes, int n_in,
                              void* d_out, int out_size) {
    const float* x      = (const float*)d_in[0];
    const float* means  = (const float*)d_in[1];
    const float* sigmas = (const float*)d_in[2];
    const float* values = (const float*)d_in[3];
    const float* bias   = (const float*)d_in[4];
    float* y = (float*)d_out;

    // key(42) = (0,42); partitionable split: child i = threefry(key, (0,i))
    uint32_t kg0, kg1, kl0, kl1;
    tf2x32(0u, 42u, 0u, 0u, kg0, kg1);
    tf2x32(0u, 42u, 0u, 1u, kl0, kl1);

    sl_init_kernel<<<(B * OUT_DIM + 255) / 256, 256>>>(bias, y);

    dim3 grid(NCHUNK, B);
    sl_chunk_kernel<<<grid, 256>>>(x, means, sigmas, values, y,
                                   kg0, kg1, kl0, kl1);
}

// round 4
// speedup vs baseline: 1.4640x; 1.1212x over previous
#include <cuda_runtime.h>
#include <cstdint>

#define B        8
#define NPOS     4096
#define CHUNK    32
#define NCHUNK   128
#define PTS      256
#define OUT_DIM  1024
#define IN_DIM   1024
#define EPS      1e-6f
#define ROWP     36      // sprops row stride (floats): 16B-aligned, conflict-free
#define NL2E_H   (-0.72134752044448170367f)   // -0.5 * log2(e)

// ---------------------------------------------------------------------------
// Threefry-2x32, 20 rounds
// ---------------------------------------------------------------------------
__host__ __device__ __forceinline__ void tf2x32(uint32_t k0, uint32_t k1,
                                                uint32_t c0, uint32_t c1,
                                                uint32_t& o0, uint32_t& o1) {
    uint32_t ks2 = k0 ^ k1 ^ 0x1BD11BDAu;
    uint32_t x0 = c0 + k0, x1 = c1 + k1;
#define TF_ROUND(r) { x0 += x1; x1 = (x1 << (r)) | (x1 >> (32 - (r))); x1 ^= x0; }
    TF_ROUND(13) TF_ROUND(15) TF_ROUND(26) TF_ROUND(6)
    x0 += k1;  x1 += ks2 + 1u;
    TF_ROUND(17) TF_ROUND(29) TF_ROUND(16) TF_ROUND(24)
    x0 += ks2; x1 += k0 + 2u;
    TF_ROUND(13) TF_ROUND(15) TF_ROUND(26) TF_ROUND(6)
    x0 += k0;  x1 += k1 + 3u;
    TF_ROUND(17) TF_ROUND(29) TF_ROUND(16) TF_ROUND(24)
    x0 += k1;  x1 += ks2 + 4u;
    TF_ROUND(13) TF_ROUND(15) TF_ROUND(26) TF_ROUND(6)
    x0 += ks2; x1 += k0 + 5u;
#undef TF_ROUND
    o0 = x0; o1 = x1;
}

// partitionable random_bits (32-bit): bits(e) = x0^x1 of threefry(key,(0,e))
__device__ __forceinline__ uint32_t rand_bits_part(uint32_t k0, uint32_t k1,
                                                   uint32_t e) {
    uint32_t o0, o1;
    tf2x32(k0, k1, 0u, e, o0, o1);
    return o0 ^ o1;
}

__device__ __forceinline__ float u01(uint32_t bits) {
    return __uint_as_float((bits >> 9) | 0x3F800000u) - 1.0f;
}

// raw MUFU.EX2 (2^x); relative error ~5e-7, well under the 1e-3 budget
__device__ __forceinline__ float ex2(float x) {
    float r;
    asm("ex2.approx.f32 %0, %1;" : "=f"(r) : "f"(x));
    return r;
}

// ---------------------------------------------------------------------------
__global__ void sl_init_kernel(const float* __restrict__ bias,
                               float* __restrict__ y) {
    int i = blockIdx.x * blockDim.x + threadIdx.x;
    if (i < B * OUT_DIM) y[i] = bias[i & (OUT_DIM - 1)];
}

// ---------------------------------------------------------------------------
// One block per (chunk, batch); 256 threads = 256 candidate points.
// ---------------------------------------------------------------------------
__global__ __launch_bounds__(256, 5) void sl_chunk_kernel(
    const float* __restrict__ x,
    const float* __restrict__ means,
    const float* __restrict__ sigmas,
    const float* __restrict__ values,
    float* __restrict__ y,
    uint32_t kg0, uint32_t kg1, uint32_t kl0, uint32_t kl1)
{
    // sg: (m0, m1, -0.5*log2e/(eps+s0), -0.5*log2e/(eps+s1))
    __shared__ __align__(16) float4 sg[CHUNK];
    __shared__ float sval[CHUNK];
    __shared__ __align__(16) int   scode[PTS];
    __shared__ __align__(16) float sprops[PTS][ROWP];
    __shared__ float spart[8][CHUNK];
    __shared__ __align__(16) float svv[CHUNK];

    const int tid   = threadIdx.x;
    const int cc    = blockIdx.x;
    const int bb    = blockIdx.y;
    const int k     = tid >> 3;
    const int which = tid & 7;
    const int lane  = tid & 31;
    const int warp  = tid >> 5;

    if (tid < CHUNK) {
        int pos = bb * NPOS + cc * CHUNK + tid;
        float2 mm = ((const float2*)means)[pos];
        float2 ss = ((const float2*)sigmas)[pos];
        sg[tid] = make_float4(mm.x, mm.y,
                              NL2E_H / (EPS + ss.x), NL2E_H / (EPS + ss.y));
        sval[tid] = values[pos];
    }
    __syncthreads();

    const float4 g = sg[k];
    const float m0 = g.x, m1 = g.y;
    int o, j;

    if (which < 4) {
        // FLOOR_MASK rows: (T,T),(T,F),(F,T),(F,F); True -> floor
        float f0 = (which < 2)        ? floorf(m0) : ceilf(m0);
        float f1 = ((which & 1) == 0) ? floorf(m1) : ceilf(m1);
        o = (int)f0;
        j = (int)f1;
    } else {
        // global (which 4,5) / local (which 6,7) share element index; key differs
        bool isg = (which < 6);
        uint32_t e  = (uint32_t)(bb * 16384 + cc * 128 + k * 4 + (which & 1) * 2);
        uint32_t key0 = isg ? kg0 : kl0;
        uint32_t key1 = isg ? kg1 : kl1;
        float u0 = u01(rand_bits_part(key0, key1, e));
        float u1 = u01(rand_bits_part(key0, key1, e + 1));
        float lu0 = __fmul_rn(u0, 1.0f - EPS);
        float lu1 = __fmul_rn(u1, 1.0f - EPS);
        if (isg) {
            o = (int)floorf(__fmul_rn(lu0, 1024.0f));
            j = (int)floorf(__fmul_rn(lu1, 1024.0f));
        } else {
            float mn0 = rintf(m0), mn1 = rintf(m1);
            float lo0 = mn0 - 8.0f, lo1 = mn1 - 8.0f;
            if (lo0 < 0.0f) lo0 = 0.0f;
            if (mn0 + 8.0f > 1024.0f) lo0 = 1008.0f;
            if (lo1 < 0.0f) lo1 = 0.0f;
            if (mn1 + 8.0f > 1024.0f) lo1 = 1008.0f;
            o = (int)__fadd_rn(__fmul_rn(lu0, 16.0f), lo0);
            j = (int)__fadd_rn(__fmul_rn(lu1, 16.0f), lo1);
        }
    }

    const int code = o * IN_DIM + j;
    scode[tid] = code;
    __syncthreads();

    // duplicate detection: match_any within own warp + vec4 scan of earlier warps
    unsigned mmask = __match_any_sync(0xffffffffu, code);
    bool dup = (mmask & ((1u << lane) - 1u)) != 0u;
    {
        const int4* sc4 = (const int4*)scode;
        const int n4 = warp * 8;
        for (int t = 0; t < n4; t++) {
            int4 c = sc4[t];
            dup |= (c.x == code) | (c.y == code) | (c.z == code) | (c.w == code);
        }
    }

    // densities row: 4 at a time in registers, STS.128
    const float po = (float)o, pj = (float)j;
    const float zmask = dup ? 0.0f : 1.0f;
    #pragma unroll
    for (int q = 0; q < CHUNK / 4; q++) {
        float pv[4];
        #pragma unroll
        for (int u = 0; u < 4; u++) {
            float4 gk = sg[q * 4 + u];
            float d0 = po - gk.x;
            float d1 = pj - gk.y;
            // s already includes the -0.5*log2(e) factor (folded into gk.z/gk.w)
            float s  = fmaf(d0 * d0, gk.z, d1 * d1 * gk.w);
            pv[u] = zmask * ex2(s);
        }
        *(float4*)&sprops[tid][q * 4] =
            make_float4(pv[0], pv[1], pv[2], pv[3]);
    }
    __syncthreads();

    // column sums over 256 points (8 groups x 32 rows, then stage 2)
    {
        int col = lane, grp = warp;
        float s = 0.0f;
        int r0 = grp * 32;
        #pragma unroll 8
        for (int r = 0; r < 32; r++) s += sprops[r0 + r][col];
        spart[grp][col] = s;
    }
    __syncthreads();
    if (tid < CHUNK) {
        float s = 0.0f;
        #pragma unroll
        for (int gI = 0; gI < 8; gI++) s += spart[gI][tid];
        svv[tid] = sval[tid] / s;
    }
    __syncthreads();

    if (!dup) {
        const float4* row = (const float4*)&sprops[tid][0];
        const float4* vv4 = (const float4*)svv;
        float v = 0.0f;
        #pragma unroll
        for (int q = 0; q < CHUNK / 4; q++) {
            float4 p = row[q];
            float4 w = vv4[q];
            v = fmaf(p.x, w.x, v);
            v = fmaf(p.y, w.y, v);
            v = fmaf(p.z, w.z, v);
            v = fmaf(p.w, w.w, v);
        }
        float contrib = v * x[bb * IN_DIM + j];
        atomicAdd(&y[bb * OUT_DIM + o], contrib);
    }
}

// ---------------------------------------------------------------------------
extern "C" void kernel_launch(void* const* d_in, const int* in_sizes, int n_in,
                              void* d_out, int out_size) {
    const float* x      = (const float*)d_in[0];
    const float* means  = (const float*)d_in[1];
    const float* sigmas = (const float*)d_in[2];
    const float* values = (const float*)d_in[3];
    const float* bias   = (const float*)d_in[4];
    float* y = (float*)d_out;

    // key(42) = (0,42); partitionable split: child i = threefry(key, (0,i))
    uint32_t kg0, kg1, kl0, kl1;
    tf2x32(0u, 42u, 0u, 0u, kg0, kg1);
    tf2x32(0u, 42u, 0u, 1u, kl0, kl1);

    sl_init_kernel<<<(B * OUT_DIM + 255) / 256, 256>>>(bias, y);

    dim3 grid(NCHUNK, B);
    sl_chunk_kernel<<<grid, 256>>>(x, means, sigmas, values, y,
                                   kg0, kg1, kl0, kl1);
}